// round 2
// baseline (speedup 1.0000x reference)
#include <cuda_runtime.h>

#define N_TOK 2048
#define K_TOK 128
#define D_DIM 768
#define H_DIM 512

// Scratch (device globals: no allocation allowed in kernel_launch)
__device__ float g_img[N_TOK * H_DIM];    // [n][h]  img @ W1[:D]
__device__ float g_txtT[H_DIM * K_TOK];   // [h][k]  (txt @ W1[D:]) + b1, transposed

// ---------- packed f32x2 helpers ----------
__device__ __forceinline__ unsigned long long pack2(float lo, float hi) {
    unsigned long long r;
    asm("mov.b64 %0, {%1, %2};" : "=l"(r) : "f"(lo), "f"(hi));
    return r;
}
__device__ __forceinline__ void unpack2(unsigned long long v, float& lo, float& hi) {
    asm("mov.b64 {%0, %1}, %2;" : "=f"(lo), "=f"(hi) : "l"(v));
}
__device__ __forceinline__ void fma2(unsigned long long& d, unsigned long long a,
                                     unsigned long long b) {
    asm("fma.rn.f32x2 %0, %1, %2, %0;" : "+l"(d) : "l"(a), "l"(b));
}
__device__ __forceinline__ unsigned long long add2(unsigned long long a,
                                                   unsigned long long b) {
    unsigned long long r;
    asm("add.rn.f32x2 %0, %1, %2;" : "=l"(r) : "l"(a), "l"(b));
    return r;
}
__device__ __forceinline__ unsigned long long relu2(unsigned long long v) {
    float lo, hi;
    unpack2(v, lo, hi);
    return pack2(fmaxf(lo, 0.f), fmaxf(hi, 0.f));
}

// ---------- combined projection GEMM ----------
// One launch covers BOTH projections (no serialized tiny kernel):
//   blocks [0, 512): img @ W1[:D]            -> g_img   [n][h]
//   blocks [512,544): txt @ W1[D:] + b1      -> g_txtT  [h][k] (transposed)
// Tile: BM=32, BN=64, BK=16, 128 threads, per-thread 2m x 8n (f32x2 pairs).
__global__ __launch_bounds__(128) void proj_combined(
    const float* __restrict__ img, const float* __restrict__ txt,
    const float* __restrict__ W1, const float* __restrict__ b1)
{
    __shared__ float As[32][20];   // [m][k], padded
    __shared__ float Ws[16][64];   // [k][n], row = 256B (16B-aligned LDS.128 reads)

    const int t  = threadIdx.x;
    const int tx = t & 7;          // n: 8 groups of 8
    const int ty = t >> 3;         // m: 16 groups of 2

    const int b = blockIdx.x;
    const bool is_txt = (b >= 512);
    const int lb = is_txt ? (b - 512) : b;
    const int m0 = (lb >> 3) * 32;
    const int n0 = (lb & 7) * 64;

    const float* __restrict__ A = is_txt ? txt : img;
    const float* __restrict__ W = is_txt ? (W1 + D_DIM * H_DIM) : W1;

    // loaders: A tile 32x16 = 128 float4 (1/thread); W tile 16x64 = 256 float4 (2/thread)
    const int ar = t >> 2, ac = (t & 3) << 2;
    const int wr0 = t >> 4,        wc0 = (t & 15) << 2;
    const int wr1 = (t + 128) >> 4, wc1 = ((t + 128) & 15) << 2;

    float4 pa  = *(const float4*)&A[(m0 + ar) * D_DIM + ac];
    float4 pw0 = *(const float4*)&W[wr0 * H_DIM + n0 + wc0];
    float4 pw1 = *(const float4*)&W[wr1 * H_DIM + n0 + wc1];

    unsigned long long acc[2][4];
    #pragma unroll
    for (int i = 0; i < 2; i++)
        #pragma unroll
        for (int p = 0; p < 4; p++) acc[i][p] = 0ull;

    const int NIT = D_DIM / 16;    // 48
    for (int kt = 0; kt < NIT; kt++) {
        *(float4*)&As[ar][ac]   = pa;
        *(float4*)&Ws[wr0][wc0] = pw0;
        *(float4*)&Ws[wr1][wc1] = pw1;
        __syncthreads();

        if (kt + 1 < NIT) {        // register double-buffer next tile
            const int k0 = (kt + 1) * 16;
            pa  = *(const float4*)&A[(m0 + ar) * D_DIM + k0 + ac];
            pw0 = *(const float4*)&W[(k0 + wr0) * H_DIM + n0 + wc0];
            pw1 = *(const float4*)&W[(k0 + wr1) * H_DIM + n0 + wc1];
        }

        #pragma unroll
        for (int kk = 0; kk < 16; kk++) {
            // 8 B-values as 2x LDS.128 -> directly usable as f32x2 reg pairs
            const ulonglong2 bq0 = *(const ulonglong2*)&Ws[kk][tx << 3];
            const ulonglong2 bq1 = *(const ulonglong2*)&Ws[kk][(tx << 3) + 4];
            #pragma unroll
            for (int i = 0; i < 2; i++) {
                const float a = As[(ty << 1) + i][kk];
                const unsigned long long a2 = pack2(a, a);
                fma2(acc[i][0], a2, bq0.x);
                fma2(acc[i][1], a2, bq0.y);
                fma2(acc[i][2], a2, bq1.x);
                fma2(acc[i][3], a2, bq1.y);
            }
        }
        __syncthreads();
    }

    #pragma unroll
    for (int i = 0; i < 2; i++) {
        const int m = m0 + (ty << 1) + i;
        if (!is_txt) {
            float4 v0, v1;
            unpack2(acc[i][0], v0.x, v0.y);
            unpack2(acc[i][1], v0.z, v0.w);
            unpack2(acc[i][2], v1.x, v1.y);
            unpack2(acc[i][3], v1.z, v1.w);
            *(float4*)&g_img[m * H_DIM + n0 + (tx << 3)]     = v0;
            *(float4*)&g_img[m * H_DIM + n0 + (tx << 3) + 4] = v1;
        } else {
            #pragma unroll
            for (int p = 0; p < 4; p++) {
                float lo, hi;
                unpack2(acc[i][p], lo, hi);
                const int n = n0 + (tx << 3) + (p << 1);
                g_txtT[n * K_TOK + m]       = lo + __ldg(&b1[n]);
                g_txtT[(n + 1) * K_TOK + m] = hi + __ldg(&b1[n + 1]);
            }
        }
    }
}

// ---------- fused relu-dot: out[n,k] = b2 + sum_h relu(img[n,h]+txtT[h,k])*W2[h]
// Block: 16n x 128k, 256 threads, per-thread 2n x 4k (2 f32x2 k-pairs). H chunk 64.
// All hot-loop math packed: add.f32x2 + 2 FMNMX (alu pipe) + fma.f32x2 per 2 terms.
__global__ __launch_bounds__(256) void fused_kernel(
    const float* __restrict__ W2, const float* __restrict__ b2,
    float* __restrict__ out)
{
    __shared__ float t_s[64][128];                 // [h][k]  32 KB (16B-aligned rows)
    __shared__ unsigned long long a2_s[16][64];    // [n][h]  (a,a) pairs, 8 KB
    __shared__ unsigned long long w2p[H_DIM];      // (w,w) pairs, 4 KB

    const int t  = threadIdx.x;
    const int tx = t & 31;           // k: 32 groups of 4
    const int ty = t >> 5;           // n: 8 warps, 2 rows each
    const int nbase = blockIdx.x * 16;

    {   // pre-duplicate W2 into (w,w) u64 pairs
        const float w0 = W2[t],       w1 = W2[t + 256];
        w2p[t]       = pack2(w0, w0);
        w2p[t + 256] = pack2(w1, w1);
    }

    unsigned long long acc00 = 0, acc01 = 0, acc10 = 0, acc11 = 0;

    const int an  = t >> 4;          // n row for a-tile load (0..15)
    const int ah4 = t & 15;          // float4 index along h

    for (int hc = 0; hc < 8; hc++) {
        const int hb = hc * 64;
        __syncthreads();
        {   // a tile: 16n x 64h, stored as duplicated pairs [n][h]
            const float4 av =
                *(const float4*)&g_img[(nbase + an) * H_DIM + hb + (ah4 << 2)];
            a2_s[an][(ah4 << 2) + 0] = pack2(av.x, av.x);
            a2_s[an][(ah4 << 2) + 1] = pack2(av.y, av.y);
            a2_s[an][(ah4 << 2) + 2] = pack2(av.z, av.z);
            a2_s[an][(ah4 << 2) + 3] = pack2(av.w, av.w);
        }
        // t tile: 64h x 128k, [h][k] in gmem -> coalesced float4
        #pragma unroll
        for (int i = 0; i < 8; i++) {
            const int fid = i * 256 + t;
            const int h = fid >> 5, k4 = fid & 31;
            *(float4*)&t_s[h][k4 << 2] =
                *(const float4*)&g_txtT[(hb + h) * K_TOK + (k4 << 2)];
        }
        __syncthreads();

        #pragma unroll 8
        for (int h = 0; h < 64; h++) {
            const unsigned long long ww = w2p[hb + h];
            const unsigned long long a0 = a2_s[(ty << 1) + 0][h];
            const unsigned long long a1 = a2_s[(ty << 1) + 1][h];
            const ulonglong2 tq = *(const ulonglong2*)&t_s[h][tx << 2];
            fma2(acc00, relu2(add2(a0, tq.x)), ww);
            fma2(acc01, relu2(add2(a0, tq.y)), ww);
            fma2(acc10, relu2(add2(a1, tq.x)), ww);
            fma2(acc11, relu2(add2(a1, tq.y)), ww);
        }
    }

    const float bb = b2[0];
    {
        float4 v;
        unpack2(acc00, v.x, v.y);
        unpack2(acc01, v.z, v.w);
        v.x += bb; v.y += bb; v.z += bb; v.w += bb;
        *(float4*)&out[(nbase + (ty << 1)) * K_TOK + (tx << 2)] = v;
    }
    {
        float4 v;
        unpack2(acc10, v.x, v.y);
        unpack2(acc11, v.z, v.w);
        v.x += bb; v.y += bb; v.z += bb; v.w += bb;
        *(float4*)&out[(nbase + (ty << 1) + 1) * K_TOK + (tx << 2)] = v;
    }
}

extern "C" void kernel_launch(void* const* d_in, const int* in_sizes, int n_in,
                              void* d_out, int out_size) {
    const float* img = (const float*)d_in[0];   // (2048, 768)
    const float* txt = (const float*)d_in[1];   // (128, 768)
    const float* W1  = (const float*)d_in[2];   // (1536, 512)
    const float* b1  = (const float*)d_in[3];   // (512,)
    const float* W2  = (const float*)d_in[4];   // (512, 1)
    const float* b2  = (const float*)d_in[5];   // (1,)
    float* out = (float*)d_out;                 // (2048, 128)

    // both projections in ONE launch: 512 img tiles + 32 txt tiles
    proj_combined<<<544, 128>>>(img, txt, W1, b1);
    // fused relu-dot epilogue
    fused_kernel<<<N_TOK / 16, 256>>>(W2, b2, out);
}

// round 3
// speedup vs baseline: 1.5706x; 1.5706x over previous
#include <cuda_runtime.h>

#define N_TOK 2048
#define K_TOK 128
#define D_DIM 768
#define H_DIM 512

// Scratch (device globals: no allocation allowed in kernel_launch)
__device__ float g_img[N_TOK * H_DIM];        // [n][h]
__device__ float g_txtT[H_DIM * K_TOK];       // [h][k] (+b1), transposed
__device__ float g_part[4 * N_TOK * K_TOK];   // h-split partials

typedef unsigned long long u64;

// ---------- packed f32x2 helpers ----------
__device__ __forceinline__ u64 pack2(float lo, float hi) {
    u64 r;
    asm("mov.b64 %0, {%1, %2};" : "=l"(r) : "f"(lo), "f"(hi));
    return r;
}
__device__ __forceinline__ void unpack2(u64 v, float& lo, float& hi) {
    asm("mov.b64 {%0, %1}, %2;" : "=f"(lo), "=f"(hi) : "l"(v));
}
__device__ __forceinline__ void fma2(u64& d, u64 a, u64 b) {
    asm("fma.rn.f32x2 %0, %1, %2, %0;" : "+l"(d) : "l"(a), "l"(b));
}
__device__ __forceinline__ u64 add2(u64 a, u64 b) {
    u64 r;
    asm("add.rn.f32x2 %0, %1, %2;" : "=l"(r) : "l"(a), "l"(b));
    return r;
}
__device__ __forceinline__ u64 relu2(u64 v) {
    float lo, hi;
    unpack2(v, lo, hi);
    return pack2(fmaxf(lo, 0.f), fmaxf(hi, 0.f));
}

// ============ projection GEMM ============
// blocks [0,128): img @ W1[:D] -> g_img ; blocks [128,136): txt @ W1[D:] + b1 -> g_txtT
// BM=64, BN=128, BK=16, 128 threads, 8m x 8n per thread, f32x2 accumulators.
// A tile stored PRE-DUPLICATED (a,a) in [k][m] u64 layout -> A-frag via LDS.128, no MOVs.
__global__ __launch_bounds__(128) void proj_kernel(
    const float* __restrict__ img, const float* __restrict__ txt,
    const float* __restrict__ W1, const float* __restrict__ b1)
{
    __shared__ __align__(16) u64   As2[2][16][64];    // [buf][k][m] (a,a) pairs, 16 KB
    __shared__ __align__(16) float Ws [2][16][128];   // [buf][k][n], 16 KB

    const int t    = threadIdx.x;
    const int lane = t & 31;
    const int warp = t >> 5;
    const int mg   = lane >> 3;        // 4 m-groups
    const int ngx  = lane & 7;         // 8 n-groups
    const int wm   = warp >> 1;        // 2
    const int wn   = warp & 1;         // 2
    const int mb   = wm * 32 + mg * 8; // thread m base within block
    const int nb2  = wn * 64 + ngx * 8;// thread n base within block

    const int b = blockIdx.x;
    const bool is_txt = (b >= 128);
    const int lb = is_txt ? (b - 128) : b;
    const int m0 = (lb >> 2) * 64;
    const int n0 = (lb & 3) * 128;

    const float* __restrict__ A = is_txt ? txt : img;
    const float* __restrict__ W = is_txt ? (W1 + D_DIM * H_DIM) : W1;

    // A loader: 64x16 = 256 float4, 2/thread
    const int ar0 = t >> 2,          ac0 = (t & 3) << 2;
    const int ar1 = (t + 128) >> 2,  ac1 = ((t + 128) & 3) << 2;

    float4 pa0 = *(const float4*)&A[(m0 + ar0) * D_DIM + ac0];
    float4 pa1 = *(const float4*)&A[(m0 + ar1) * D_DIM + ac1];
    // W loader: 16x128 = 512 float4, 4/thread
    float4 pw[4];
    #pragma unroll
    for (int i = 0; i < 4; i++) {
        const int fid = t + i * 128;
        pw[i] = *(const float4*)&W[(fid >> 5) * H_DIM + n0 + ((fid & 31) << 2)];
    }

    u64 acc[8][4];
    #pragma unroll
    for (int i = 0; i < 8; i++)
        #pragma unroll
        for (int p = 0; p < 4; p++) acc[i][p] = 0ull;

    // store stage 0
    {
        As2[0][ac0 + 0][ar0] = pack2(pa0.x, pa0.x);
        As2[0][ac0 + 1][ar0] = pack2(pa0.y, pa0.y);
        As2[0][ac0 + 2][ar0] = pack2(pa0.z, pa0.z);
        As2[0][ac0 + 3][ar0] = pack2(pa0.w, pa0.w);
        As2[0][ac1 + 0][ar1] = pack2(pa1.x, pa1.x);
        As2[0][ac1 + 1][ar1] = pack2(pa1.y, pa1.y);
        As2[0][ac1 + 2][ar1] = pack2(pa1.z, pa1.z);
        As2[0][ac1 + 3][ar1] = pack2(pa1.w, pa1.w);
        #pragma unroll
        for (int i = 0; i < 4; i++) {
            const int fid = t + i * 128;
            *(float4*)&Ws[0][fid >> 5][(fid & 31) << 2] = pw[i];
        }
    }
    __syncthreads();

    const int NIT = D_DIM / 16;  // 48
    for (int kt = 0; kt < NIT; kt++) {
        const int buf = kt & 1;

        if (kt + 1 < NIT) {   // prefetch next stage into registers
            const int k0 = (kt + 1) * 16;
            pa0 = *(const float4*)&A[(m0 + ar0) * D_DIM + k0 + ac0];
            pa1 = *(const float4*)&A[(m0 + ar1) * D_DIM + k0 + ac1];
            #pragma unroll
            for (int i = 0; i < 4; i++) {
                const int fid = t + i * 128;
                pw[i] = *(const float4*)&W[(k0 + (fid >> 5)) * H_DIM + n0 + ((fid & 31) << 2)];
            }
        }

        #pragma unroll
        for (int kk = 0; kk < 16; kk++) {
            const u64* ap = &As2[buf][kk][mb];
            const ulonglong2 a01 = *(const ulonglong2*)(ap + 0);
            const ulonglong2 a23 = *(const ulonglong2*)(ap + 2);
            const ulonglong2 a45 = *(const ulonglong2*)(ap + 4);
            const ulonglong2 a67 = *(const ulonglong2*)(ap + 6);
            const ulonglong2 bq0 = *(const ulonglong2*)&Ws[buf][kk][nb2];
            const ulonglong2 bq1 = *(const ulonglong2*)&Ws[buf][kk][nb2 + 4];
            const u64 av[8] = {a01.x, a01.y, a23.x, a23.y, a45.x, a45.y, a67.x, a67.y};
            #pragma unroll
            for (int i = 0; i < 8; i++) {
                fma2(acc[i][0], av[i], bq0.x);
                fma2(acc[i][1], av[i], bq0.y);
                fma2(acc[i][2], av[i], bq1.x);
                fma2(acc[i][3], av[i], bq1.y);
            }
        }

        if (kt + 1 < NIT) {   // store next stage
            const int nb = buf ^ 1;
            As2[nb][ac0 + 0][ar0] = pack2(pa0.x, pa0.x);
            As2[nb][ac0 + 1][ar0] = pack2(pa0.y, pa0.y);
            As2[nb][ac0 + 2][ar0] = pack2(pa0.z, pa0.z);
            As2[nb][ac0 + 3][ar0] = pack2(pa0.w, pa0.w);
            As2[nb][ac1 + 0][ar1] = pack2(pa1.x, pa1.x);
            As2[nb][ac1 + 1][ar1] = pack2(pa1.y, pa1.y);
            As2[nb][ac1 + 2][ar1] = pack2(pa1.z, pa1.z);
            As2[nb][ac1 + 3][ar1] = pack2(pa1.w, pa1.w);
            #pragma unroll
            for (int i = 0; i < 4; i++) {
                const int fid = t + i * 128;
                *(float4*)&Ws[nb][fid >> 5][(fid & 31) << 2] = pw[i];
            }
        }
        __syncthreads();
    }

    // epilogue
    #pragma unroll
    for (int i = 0; i < 8; i++) {
        const int m = m0 + mb + i;
        if (!is_txt) {
            float4 v0, v1;
            unpack2(acc[i][0], v0.x, v0.y);
            unpack2(acc[i][1], v0.z, v0.w);
            unpack2(acc[i][2], v1.x, v1.y);
            unpack2(acc[i][3], v1.z, v1.w);
            *(float4*)&g_img[m * H_DIM + n0 + nb2]     = v0;
            *(float4*)&g_img[m * H_DIM + n0 + nb2 + 4] = v1;
        } else {
            #pragma unroll
            for (int p = 0; p < 4; p++) {
                float lo, hi;
                unpack2(acc[i][p], lo, hi);
                const int n = n0 + nb2 + (p << 1);
                g_txtT[n * K_TOK + m]       = lo + __ldg(&b1[n]);
                g_txtT[(n + 1) * K_TOK + m] = hi + __ldg(&b1[n + 1]);
            }
        }
    }
}

// ============ fused relu-dot with h-split ============
// part[hs][n][k] = sum_{h in split hs} relu(img[n,h]+txtT[h,k]) * W2[h]
// grid 256 = 64 n-blocks x 4 h-splits. Block: 32n x 128k x 128h.
// 128 threads, 8n x 4k per thread. h chunks of 32, double-buffered.
__global__ __launch_bounds__(128) void fused_kernel(
    const float* __restrict__ W2, float* __restrict__ part)
{
    __shared__ __align__(16) float t_s [2][32][128];  // [buf][h][k] 32 KB
    __shared__ __align__(16) u64   a2_s[2][32][32];   // [buf][h][n] (a,a) 16 KB
    __shared__ u64 w2p[128];                          // (w,w) for this h-split

    const int t  = threadIdx.x;
    const int kg = t & 31;          // 32 k-groups of 4
    const int ng = t >> 5;          // 4 n-groups of 8 (constant per warp -> broadcast)
    const int b  = blockIdx.x;
    const int nb = b & 63;
    const int hs = b >> 6;
    const int hb0 = hs * 128;
    const int nrow0 = nb * 32;

    { const float w = W2[hb0 + t]; w2p[t] = pack2(w, w); }

    // loaders
    const int tn  = t >> 3;         // 0..15 (a rows tn and tn+16)
    const int th4 = t & 7;          // a float4 along h

    float4 pt[8], pa0, pa1;

    // prefetch chunk 0
    {
        const int hbase = hb0;
        #pragma unroll
        for (int i = 0; i < 8; i++) {
            const int fid = i * 128 + t;
            pt[i] = *(const float4*)&g_txtT[(hbase + (fid >> 5)) * K_TOK + ((fid & 31) << 2)];
        }
        pa0 = *(const float4*)&g_img[(nrow0 + tn)      * H_DIM + hbase + (th4 << 2)];
        pa1 = *(const float4*)&g_img[(nrow0 + tn + 16) * H_DIM + hbase + (th4 << 2)];
    }
    // store chunk 0
    {
        #pragma unroll
        for (int i = 0; i < 8; i++) {
            const int fid = i * 128 + t;
            *(float4*)&t_s[0][fid >> 5][(fid & 31) << 2] = pt[i];
        }
        a2_s[0][(th4 << 2) + 0][tn] = pack2(pa0.x, pa0.x);
        a2_s[0][(th4 << 2) + 1][tn] = pack2(pa0.y, pa0.y);
        a2_s[0][(th4 << 2) + 2][tn] = pack2(pa0.z, pa0.z);
        a2_s[0][(th4 << 2) + 3][tn] = pack2(pa0.w, pa0.w);
        a2_s[0][(th4 << 2) + 0][tn + 16] = pack2(pa1.x, pa1.x);
        a2_s[0][(th4 << 2) + 1][tn + 16] = pack2(pa1.y, pa1.y);
        a2_s[0][(th4 << 2) + 2][tn + 16] = pack2(pa1.z, pa1.z);
        a2_s[0][(th4 << 2) + 3][tn + 16] = pack2(pa1.w, pa1.w);
    }
    __syncthreads();

    u64 acc[8][2];
    #pragma unroll
    for (int i = 0; i < 8; i++) { acc[i][0] = 0ull; acc[i][1] = 0ull; }

    for (int c = 0; c < 4; c++) {
        const int buf = c & 1;

        if (c + 1 < 4) {   // prefetch next chunk
            const int hbase = hb0 + (c + 1) * 32;
            #pragma unroll
            for (int i = 0; i < 8; i++) {
                const int fid = i * 128 + t;
                pt[i] = *(const float4*)&g_txtT[(hbase + (fid >> 5)) * K_TOK + ((fid & 31) << 2)];
            }
            pa0 = *(const float4*)&g_img[(nrow0 + tn)      * H_DIM + hbase + (th4 << 2)];
            pa1 = *(const float4*)&g_img[(nrow0 + tn + 16) * H_DIM + hbase + (th4 << 2)];
        }

        #pragma unroll 8
        for (int h = 0; h < 32; h++) {
            const u64 ww = w2p[c * 32 + h];
            const u64* ap = &a2_s[buf][h][ng << 3];
            const ulonglong2 qa0 = *(const ulonglong2*)(ap + 0);
            const ulonglong2 qa1 = *(const ulonglong2*)(ap + 2);
            const ulonglong2 qa2 = *(const ulonglong2*)(ap + 4);
            const ulonglong2 qa3 = *(const ulonglong2*)(ap + 6);
            const ulonglong2 tq  = *(const ulonglong2*)&t_s[buf][h][kg << 2];
            const u64 av[8] = {qa0.x, qa0.y, qa1.x, qa1.y, qa2.x, qa2.y, qa3.x, qa3.y};
            #pragma unroll
            for (int i = 0; i < 8; i++) {
                fma2(acc[i][0], relu2(add2(av[i], tq.x)), ww);
                fma2(acc[i][1], relu2(add2(av[i], tq.y)), ww);
            }
        }

        if (c + 1 < 4) {
            const int nbuf = buf ^ 1;
            #pragma unroll
            for (int i = 0; i < 8; i++) {
                const int fid = i * 128 + t;
                *(float4*)&t_s[nbuf][fid >> 5][(fid & 31) << 2] = pt[i];
            }
            a2_s[nbuf][(th4 << 2) + 0][tn] = pack2(pa0.x, pa0.x);
            a2_s[nbuf][(th4 << 2) + 1][tn] = pack2(pa0.y, pa0.y);
            a2_s[nbuf][(th4 << 2) + 2][tn] = pack2(pa0.z, pa0.z);
            a2_s[nbuf][(th4 << 2) + 3][tn] = pack2(pa0.w, pa0.w);
            a2_s[nbuf][(th4 << 2) + 0][tn + 16] = pack2(pa1.x, pa1.x);
            a2_s[nbuf][(th4 << 2) + 1][tn + 16] = pack2(pa1.y, pa1.y);
            a2_s[nbuf][(th4 << 2) + 2][tn + 16] = pack2(pa1.z, pa1.z);
            a2_s[nbuf][(th4 << 2) + 3][tn + 16] = pack2(pa1.w, pa1.w);
        }
        __syncthreads();
    }

    // write partials: thread covers 8 n rows x 4 k
    float* p = part + hs * (N_TOK * K_TOK);
    #pragma unroll
    for (int i = 0; i < 8; i++) {
        const int n = nrow0 + (ng << 3) + i;
        float4 v;
        unpack2(acc[i][0], v.x, v.y);
        unpack2(acc[i][1], v.z, v.w);
        *(float4*)&p[n * K_TOK + (kg << 2)] = v;
    }
}

// ============ combine: out = sum of 4 partials + b2 ============
__global__ __launch_bounds__(128) void combine_kernel(
    const float* __restrict__ b2, float* __restrict__ out)
{
    const int idx = (blockIdx.x * 128 + threadIdx.x) * 4;
    const float4 p0 = *(const float4*)&g_part[idx];
    const float4 p1 = *(const float4*)&g_part[N_TOK * K_TOK + idx];
    const float4 p2 = *(const float4*)&g_part[2 * N_TOK * K_TOK + idx];
    const float4 p3 = *(const float4*)&g_part[3 * N_TOK * K_TOK + idx];
    const float bb = b2[0];
    float4 v;
    v.x = p0.x + p1.x + p2.x + p3.x + bb;
    v.y = p0.y + p1.y + p2.y + p3.y + bb;
    v.z = p0.z + p1.z + p2.z + p3.z + bb;
    v.w = p0.w + p1.w + p2.w + p3.w + bb;
    *(float4*)&out[idx] = v;
}

extern "C" void kernel_launch(void* const* d_in, const int* in_sizes, int n_in,
                              void* d_out, int out_size) {
    const float* img = (const float*)d_in[0];   // (2048, 768)
    const float* txt = (const float*)d_in[1];   // (128, 768)
    const float* W1  = (const float*)d_in[2];   // (1536, 512)
    const float* b1  = (const float*)d_in[3];   // (512,)
    const float* W2  = (const float*)d_in[4];   // (512, 1)
    const float* b2  = (const float*)d_in[5];   // (1,)
    float* out = (float*)d_out;                 // (2048, 128)

    float* part;
    cudaGetSymbolAddress((void**)&part, g_part);

    proj_kernel<<<136, 128>>>(img, txt, W1, b1);
    fused_kernel<<<256, 128>>>(W2, part);
    combine_kernel<<<(N_TOK * K_TOK) / (128 * 4), 128>>>(b2, out);
}

// round 4
// speedup vs baseline: 1.6493x; 1.0501x over previous
#include <cuda_runtime.h>

#define N_TOK 2048
#define K_TOK 128
#define D_DIM 768
#define H_DIM 512

// Scratch (device globals: no allocation allowed in kernel_launch)
__device__ float g_img[N_TOK * H_DIM];        // [n][h]
__device__ float g_txtT[H_DIM * K_TOK];       // [h][k] (+b1), transposed
__device__ float g_part[4 * N_TOK * K_TOK];   // h-split partials

typedef unsigned long long u64;

// ---------- packed f32x2 helpers ----------
__device__ __forceinline__ u64 pack2(float lo, float hi) {
    u64 r;
    asm("mov.b64 %0, {%1, %2};" : "=l"(r) : "f"(lo), "f"(hi));
    return r;
}
__device__ __forceinline__ void unpack2(u64 v, float& lo, float& hi) {
    asm("mov.b64 {%0, %1}, %2;" : "=f"(lo), "=f"(hi) : "l"(v));
}
__device__ __forceinline__ void fma2(u64& d, u64 a, u64 b) {
    asm("fma.rn.f32x2 %0, %1, %2, %0;" : "+l"(d) : "l"(a), "l"(b));
}
__device__ __forceinline__ u64 add2(u64 a, u64 b) {
    u64 r;
    asm("add.rn.f32x2 %0, %1, %2;" : "=l"(r) : "l"(a), "l"(b));
    return r;
}
__device__ __forceinline__ u64 relu2(u64 v) {
    float lo, hi;
    unpack2(v, lo, hi);
    return pack2(fmaxf(lo, 0.f), fmaxf(hi, 0.f));
}

// ============ projection GEMM ============
// blocks [0,128): img @ W1[:D] -> g_img ; blocks [128,136): txt @ W1[D:] + b1 -> g_txtT
// BM=64, BN=128, BK=16, 256 threads (8 warps -> 2 warps/SMSP), 8m x 4n per thread.
// A tile PRE-DUPLICATED (a,a) in [k][m] u64 layout -> A-frag via LDS.128, no MOVs.
__global__ __launch_bounds__(256) void proj_kernel(
    const float* __restrict__ img, const float* __restrict__ txt,
    const float* __restrict__ W1, const float* __restrict__ b1)
{
    __shared__ __align__(16) u64   As2[2][16][64];    // [buf][k][m] (a,a) pairs, 32 KB
    __shared__ __align__(16) float Ws [2][16][128];   // [buf][k][n], 16 KB

    const int t    = threadIdx.x;
    const int lane = t & 31;
    const int warp = t >> 5;
    const int mg   = lane >> 3;          // 4 m-groups per warp
    const int ng   = lane & 7;           // 8 n-groups per warp
    const int wm   = warp >> 2;          // 2 warp-rows (m)
    const int wn   = warp & 3;           // 4 warp-cols (n)
    const int mb   = wm * 32 + mg * 8;   // thread m base (8 rows)
    const int nb2  = wn * 32 + ng * 4;   // thread n base (4 cols = 2 u64)

    const int b = blockIdx.x;
    const bool is_txt = (b >= 128);
    const int lb = is_txt ? (b - 128) : b;
    const int m0 = (lb >> 2) * 64;
    const int n0 = (lb & 3) * 128;

    const float* __restrict__ A = is_txt ? txt : img;
    const float* __restrict__ W = is_txt ? (W1 + D_DIM * H_DIM) : W1;

    // A loader: 64x16 = 256 float4 -> 1/thread (coalesced along k)
    const int ar = t >> 2, ac = (t & 3) << 2;
    // W loader: 16x128 = 512 float4 -> 2/thread
    const int w0r = t >> 5,           w0c = (t & 31) << 2;
    const int w1r = (t + 256) >> 5,   w1c = w0c;

    float4 pa  = *(const float4*)&A[(m0 + ar) * D_DIM + ac];
    float4 pw0 = *(const float4*)&W[w0r * H_DIM + n0 + w0c];
    float4 pw1 = *(const float4*)&W[w1r * H_DIM + n0 + w1c];

    u64 acc[8][2];
    #pragma unroll
    for (int i = 0; i < 8; i++) { acc[i][0] = 0ull; acc[i][1] = 0ull; }

    // store stage 0
    {
        As2[0][ac + 0][ar] = pack2(pa.x, pa.x);
        As2[0][ac + 1][ar] = pack2(pa.y, pa.y);
        As2[0][ac + 2][ar] = pack2(pa.z, pa.z);
        As2[0][ac + 3][ar] = pack2(pa.w, pa.w);
        *(float4*)&Ws[0][w0r][w0c] = pw0;
        *(float4*)&Ws[0][w1r][w1c] = pw1;
    }
    __syncthreads();

    const int NIT = D_DIM / 16;  // 48
    for (int kt = 0; kt < NIT; kt++) {
        const int buf = kt & 1;

        if (kt + 1 < NIT) {   // prefetch next stage into registers
            const int k0 = (kt + 1) * 16;
            pa  = *(const float4*)&A[(m0 + ar) * D_DIM + k0 + ac];
            pw0 = *(const float4*)&W[(k0 + w0r) * H_DIM + n0 + w0c];
            pw1 = *(const float4*)&W[(k0 + w1r) * H_DIM + n0 + w1c];
        }

        #pragma unroll
        for (int kk = 0; kk < 16; kk++) {
            const u64* ap = &As2[buf][kk][mb];
            const ulonglong2 a01 = *(const ulonglong2*)(ap + 0);
            const ulonglong2 a23 = *(const ulonglong2*)(ap + 2);
            const ulonglong2 a45 = *(const ulonglong2*)(ap + 4);
            const ulonglong2 a67 = *(const ulonglong2*)(ap + 6);
            const ulonglong2 bq  = *(const ulonglong2*)&Ws[buf][kk][nb2];
            const u64 av[8] = {a01.x, a01.y, a23.x, a23.y, a45.x, a45.y, a67.x, a67.y};
            #pragma unroll
            for (int i = 0; i < 8; i++) {
                fma2(acc[i][0], av[i], bq.x);
                fma2(acc[i][1], av[i], bq.y);
            }
        }

        if (kt + 1 < NIT) {   // store next stage
            const int nb = buf ^ 1;
            As2[nb][ac + 0][ar] = pack2(pa.x, pa.x);
            As2[nb][ac + 1][ar] = pack2(pa.y, pa.y);
            As2[nb][ac + 2][ar] = pack2(pa.z, pa.z);
            As2[nb][ac + 3][ar] = pack2(pa.w, pa.w);
            *(float4*)&Ws[nb][w0r][w0c] = pw0;
            *(float4*)&Ws[nb][w1r][w1c] = pw1;
        }
        __syncthreads();
    }

    // epilogue
    #pragma unroll
    for (int i = 0; i < 8; i++) {
        const int m = m0 + mb + i;
        if (!is_txt) {
            float4 v;
            unpack2(acc[i][0], v.x, v.y);
            unpack2(acc[i][1], v.z, v.w);
            *(float4*)&g_img[m * H_DIM + n0 + nb2] = v;
        } else {
            #pragma unroll
            for (int p = 0; p < 2; p++) {
                float lo, hi;
                unpack2(acc[i][p], lo, hi);
                const int n = n0 + nb2 + (p << 1);
                g_txtT[n * K_TOK + m]       = lo + __ldg(&b1[n]);
                g_txtT[(n + 1) * K_TOK + m] = hi + __ldg(&b1[n + 1]);
            }
        }
    }
}

// ============ fused relu-dot with h-split ============
// part[hs][n][k] = sum_{h in split hs} relu(img[n,h]+txtT[h,k]) * W2[h]
// grid 256 = 64 n-blocks x 4 h-splits. Block: 32n x 128k x 128h.
// 128 threads, 8n x 4k per thread. h chunks of 32, double-buffered.
__global__ __launch_bounds__(128) void fused_kernel(
    const float* __restrict__ W2, float* __restrict__ part)
{
    __shared__ __align__(16) float t_s [2][32][128];  // [buf][h][k] 32 KB
    __shared__ __align__(16) u64   a2_s[2][32][32];   // [buf][h][n] (a,a) 16 KB
    __shared__ u64 w2p[128];                          // (w,w) for this h-split

    const int t  = threadIdx.x;
    const int kg = t & 31;          // 32 k-groups of 4
    const int ng = t >> 5;          // 4 n-groups of 8 (constant per warp -> broadcast)
    const int b  = blockIdx.x;
    const int nb = b & 63;
    const int hs = b >> 6;
    const int hb0 = hs * 128;
    const int nrow0 = nb * 32;

    { const float w = W2[hb0 + t]; w2p[t] = pack2(w, w); }

    // loaders
    const int tn  = t >> 3;         // 0..15 (a rows tn and tn+16)
    const int th4 = t & 7;          // a float4 along h

    float4 pt[8], pa0, pa1;

    // prefetch chunk 0
    {
        const int hbase = hb0;
        #pragma unroll
        for (int i = 0; i < 8; i++) {
            const int fid = i * 128 + t;
            pt[i] = *(const float4*)&g_txtT[(hbase + (fid >> 5)) * K_TOK + ((fid & 31) << 2)];
        }
        pa0 = *(const float4*)&g_img[(nrow0 + tn)      * H_DIM + hbase + (th4 << 2)];
        pa1 = *(const float4*)&g_img[(nrow0 + tn + 16) * H_DIM + hbase + (th4 << 2)];
    }
    // store chunk 0
    {
        #pragma unroll
        for (int i = 0; i < 8; i++) {
            const int fid = i * 128 + t;
            *(float4*)&t_s[0][fid >> 5][(fid & 31) << 2] = pt[i];
        }
        a2_s[0][(th4 << 2) + 0][tn] = pack2(pa0.x, pa0.x);
        a2_s[0][(th4 << 2) + 1][tn] = pack2(pa0.y, pa0.y);
        a2_s[0][(th4 << 2) + 2][tn] = pack2(pa0.z, pa0.z);
        a2_s[0][(th4 << 2) + 3][tn] = pack2(pa0.w, pa0.w);
        a2_s[0][(th4 << 2) + 0][tn + 16] = pack2(pa1.x, pa1.x);
        a2_s[0][(th4 << 2) + 1][tn + 16] = pack2(pa1.y, pa1.y);
        a2_s[0][(th4 << 2) + 2][tn + 16] = pack2(pa1.z, pa1.z);
        a2_s[0][(th4 << 2) + 3][tn + 16] = pack2(pa1.w, pa1.w);
    }
    __syncthreads();

    u64 acc[8][2];
    #pragma unroll
    for (int i = 0; i < 8; i++) { acc[i][0] = 0ull; acc[i][1] = 0ull; }

    for (int c = 0; c < 4; c++) {
        const int buf = c & 1;

        if (c + 1 < 4) {   // prefetch next chunk
            const int hbase = hb0 + (c + 1) * 32;
            #pragma unroll
            for (int i = 0; i < 8; i++) {
                const int fid = i * 128 + t;
                pt[i] = *(const float4*)&g_txtT[(hbase + (fid >> 5)) * K_TOK + ((fid & 31) << 2)];
            }
            pa0 = *(const float4*)&g_img[(nrow0 + tn)      * H_DIM + hbase + (th4 << 2)];
            pa1 = *(const float4*)&g_img[(nrow0 + tn + 16) * H_DIM + hbase + (th4 << 2)];
        }

        #pragma unroll 8
        for (int h = 0; h < 32; h++) {
            const u64 ww = w2p[c * 32 + h];
            const u64* ap = &a2_s[buf][h][ng << 3];
            const ulonglong2 qa0 = *(const ulonglong2*)(ap + 0);
            const ulonglong2 qa1 = *(const ulonglong2*)(ap + 2);
            const ulonglong2 qa2 = *(const ulonglong2*)(ap + 4);
            const ulonglong2 qa3 = *(const ulonglong2*)(ap + 6);
            const ulonglong2 tq  = *(const ulonglong2*)&t_s[buf][h][kg << 2];
            const u64 av[8] = {qa0.x, qa0.y, qa1.x, qa1.y, qa2.x, qa2.y, qa3.x, qa3.y};
            #pragma unroll
            for (int i = 0; i < 8; i++) {
                fma2(acc[i][0], relu2(add2(av[i], tq.x)), ww);
                fma2(acc[i][1], relu2(add2(av[i], tq.y)), ww);
            }
        }

        if (c + 1 < 4) {
            const int nbuf = buf ^ 1;
            #pragma unroll
            for (int i = 0; i < 8; i++) {
                const int fid = i * 128 + t;
                *(float4*)&t_s[nbuf][fid >> 5][(fid & 31) << 2] = pt[i];
            }
            a2_s[nbuf][(th4 << 2) + 0][tn] = pack2(pa0.x, pa0.x);
            a2_s[nbuf][(th4 << 2) + 1][tn] = pack2(pa0.y, pa0.y);
            a2_s[nbuf][(th4 << 2) + 2][tn] = pack2(pa0.z, pa0.z);
            a2_s[nbuf][(th4 << 2) + 3][tn] = pack2(pa0.w, pa0.w);
            a2_s[nbuf][(th4 << 2) + 0][tn + 16] = pack2(pa1.x, pa1.x);
            a2_s[nbuf][(th4 << 2) + 1][tn + 16] = pack2(pa1.y, pa1.y);
            a2_s[nbuf][(th4 << 2) + 2][tn + 16] = pack2(pa1.z, pa1.z);
            a2_s[nbuf][(th4 << 2) + 3][tn + 16] = pack2(pa1.w, pa1.w);
        }
        __syncthreads();
    }

    // write partials: thread covers 8 n rows x 4 k
    float* p = part + hs * (N_TOK * K_TOK);
    #pragma unroll
    for (int i = 0; i < 8; i++) {
        const int n = nrow0 + (ng << 3) + i;
        float4 v;
        unpack2(acc[i][0], v.x, v.y);
        unpack2(acc[i][1], v.z, v.w);
        *(float4*)&p[n * K_TOK + (kg << 2)] = v;
    }
}

// ============ combine: out = sum of 4 partials + b2 ============
__global__ __launch_bounds__(128) void combine_kernel(
    const float* __restrict__ b2, float* __restrict__ out)
{
    const int idx = (blockIdx.x * 128 + threadIdx.x) * 4;
    const float4 p0 = *(const float4*)&g_part[idx];
    const float4 p1 = *(const float4*)&g_part[N_TOK * K_TOK + idx];
    const float4 p2 = *(const float4*)&g_part[2 * N_TOK * K_TOK + idx];
    const float4 p3 = *(const float4*)&g_part[3 * N_TOK * K_TOK + idx];
    const float bb = b2[0];
    float4 v;
    v.x = p0.x + p1.x + p2.x + p3.x + bb;
    v.y = p0.y + p1.y + p2.y + p3.y + bb;
    v.z = p0.z + p1.z + p2.z + p3.z + bb;
    v.w = p0.w + p1.w + p2.w + p3.w + bb;
    *(float4*)&out[idx] = v;
}

extern "C" void kernel_launch(void* const* d_in, const int* in_sizes, int n_in,
                              void* d_out, int out_size) {
    const float* img = (const float*)d_in[0];   // (2048, 768)
    const float* txt = (const float*)d_in[1];   // (128, 768)
    const float* W1  = (const float*)d_in[2];   // (1536, 512)
    const float* b1  = (const float*)d_in[3];   // (512,)
    const float* W2  = (const float*)d_in[4];   // (512, 1)
    const float* b2  = (const float*)d_in[5];   // (1,)
    float* out = (float*)d_out;                 // (2048, 128)

    float* part;
    cudaGetSymbolAddress((void**)&part, g_part);

    proj_kernel<<<136, 256>>>(img, txt, W1, b1);
    fused_kernel<<<256, 128>>>(W2, part);
    combine_kernel<<<(N_TOK * K_TOK) / (128 * 4), 128>>>(b2, out);
}

// round 5
// speedup vs baseline: 1.7651x; 1.0703x over previous
#include <cuda_runtime.h>

#define N_TOK 2048
#define K_TOK 128
#define D_DIM 768
#define H_DIM 512

// Scratch (device globals: no allocation allowed in kernel_launch)
__device__ float g_img[N_TOK * H_DIM];        // [n][h]
__device__ float g_txtT[H_DIM * K_TOK];       // [h][k] (+b1), transposed
__device__ float g_part[4 * N_TOK * K_TOK];   // h-split partials

typedef unsigned long long u64;

// ---------- packed f32x2 helpers ----------
__device__ __forceinline__ u64 pack2(float lo, float hi) {
    u64 r;
    asm("mov.b64 %0, {%1, %2};" : "=l"(r) : "f"(lo), "f"(hi));
    return r;
}
__device__ __forceinline__ void unpack2(u64 v, float& lo, float& hi) {
    asm("mov.b64 {%0, %1}, %2;" : "=f"(lo), "=f"(hi) : "l"(v));
}
__device__ __forceinline__ void fma2(u64& d, u64 a, u64 b) {
    asm("fma.rn.f32x2 %0, %1, %2, %0;" : "+l"(d) : "l"(a), "l"(b));
}
__device__ __forceinline__ u64 add2(u64 a, u64 b) {
    u64 r;
    asm("add.rn.f32x2 %0, %1, %2;" : "=l"(r) : "l"(a), "l"(b));
    return r;
}
__device__ __forceinline__ u64 relu2(u64 v) {
    float lo, hi;
    unpack2(v, lo, hi);
    return pack2(fmaxf(lo, 0.f), fmaxf(hi, 0.f));
}

// ============ projection GEMM ============
// blocks [0,256): img @ W1[:D] -> g_img ; blocks [256,272): txt @ W1[D:] + b1 -> g_txtT
// BM=32, BN=128, BK=16, 128 threads (4 warps), 8m x 4n per thread.
// 272 blocks, ~33KB smem, ~80 regs -> 4 blocks/SM resident -> 4-5 warps/SMSP.
// A tile PRE-DUPLICATED (a,a) in [k][m] u64 layout, padded row (66) vs STS bank conflicts.
__global__ __launch_bounds__(128) void proj_kernel(
    const float* __restrict__ img, const float* __restrict__ txt,
    const float* __restrict__ W1, const float* __restrict__ b1)
{
    __shared__ __align__(16) u64   As2[2][16][66];    // [buf][k][m(+pad)] (a,a) pairs
    __shared__ __align__(16) float Ws [2][16][128];   // [buf][k][n]

    const int t    = threadIdx.x;
    const int lane = t & 31;
    const int warp = t >> 5;             // 4 warps = n quadrant
    const int mg   = lane >> 3;          // 4 m-groups
    const int ng   = lane & 7;           // 8 n-groups
    const int mb   = mg * 8;             // thread m base (8 rows, covers 32)
    const int nb2  = warp * 32 + ng * 4; // thread n base (4 cols = 2 u64)

    const int b = blockIdx.x;
    const bool is_txt = (b >= 256);
    const int lb = is_txt ? (b - 256) : b;
    const int m0 = (lb >> 2) * 32;
    const int n0 = (lb & 3) * 128;

    const float* __restrict__ A = is_txt ? txt : img;
    const float* __restrict__ W = is_txt ? (W1 + D_DIM * H_DIM) : W1;

    // A loader: 32x16 = 128 float4 -> 1/thread
    const int ar = t >> 2, ac = (t & 3) << 2;
    // W loader: 16x128 = 512 float4 -> 4/thread
    float4 pa = *(const float4*)&A[(m0 + ar) * D_DIM + ac];
    float4 pw[4];
    #pragma unroll
    for (int i = 0; i < 4; i++) {
        const int fid = t + i * 128;
        pw[i] = *(const float4*)&W[(fid >> 5) * H_DIM + n0 + ((fid & 31) << 2)];
    }

    u64 acc[8][2];
    #pragma unroll
    for (int i = 0; i < 8; i++) { acc[i][0] = 0ull; acc[i][1] = 0ull; }

    // store stage 0
    {
        As2[0][ac + 0][ar] = pack2(pa.x, pa.x);
        As2[0][ac + 1][ar] = pack2(pa.y, pa.y);
        As2[0][ac + 2][ar] = pack2(pa.z, pa.z);
        As2[0][ac + 3][ar] = pack2(pa.w, pa.w);
        #pragma unroll
        for (int i = 0; i < 4; i++) {
            const int fid = t + i * 128;
            *(float4*)&Ws[0][fid >> 5][(fid & 31) << 2] = pw[i];
        }
    }
    __syncthreads();

    const int NIT = D_DIM / 16;  // 48
    for (int kt = 0; kt < NIT; kt++) {
        const int buf = kt & 1;

        if (kt + 1 < NIT) {   // prefetch next stage into registers
            const int k0 = (kt + 1) * 16;
            pa = *(const float4*)&A[(m0 + ar) * D_DIM + k0 + ac];
            #pragma unroll
            for (int i = 0; i < 4; i++) {
                const int fid = t + i * 128;
                pw[i] = *(const float4*)&W[(k0 + (fid >> 5)) * H_DIM + n0 + ((fid & 31) << 2)];
            }
        }

        #pragma unroll
        for (int kk = 0; kk < 16; kk++) {
            const u64* ap = &As2[buf][kk][mb];
            const ulonglong2 a01 = *(const ulonglong2*)(ap + 0);
            const ulonglong2 a23 = *(const ulonglong2*)(ap + 2);
            const ulonglong2 a45 = *(const ulonglong2*)(ap + 4);
            const ulonglong2 a67 = *(const ulonglong2*)(ap + 6);
            const ulonglong2 bq  = *(const ulonglong2*)&Ws[buf][kk][nb2];
            const u64 av[8] = {a01.x, a01.y, a23.x, a23.y, a45.x, a45.y, a67.x, a67.y};
            #pragma unroll
            for (int i = 0; i < 8; i++) {
                fma2(acc[i][0], av[i], bq.x);
                fma2(acc[i][1], av[i], bq.y);
            }
        }

        if (kt + 1 < NIT) {   // store next stage
            const int nb = buf ^ 1;
            As2[nb][ac + 0][ar] = pack2(pa.x, pa.x);
            As2[nb][ac + 1][ar] = pack2(pa.y, pa.y);
            As2[nb][ac + 2][ar] = pack2(pa.z, pa.z);
            As2[nb][ac + 3][ar] = pack2(pa.w, pa.w);
            #pragma unroll
            for (int i = 0; i < 4; i++) {
                const int fid = t + i * 128;
                *(float4*)&Ws[nb][fid >> 5][(fid & 31) << 2] = pw[i];
            }
        }
        __syncthreads();
    }

    // epilogue
    #pragma unroll
    for (int i = 0; i < 8; i++) {
        const int m = m0 + mb + i;
        if (!is_txt) {
            float4 v;
            unpack2(acc[i][0], v.x, v.y);
            unpack2(acc[i][1], v.z, v.w);
            *(float4*)&g_img[m * H_DIM + n0 + nb2] = v;
        } else {
            #pragma unroll
            for (int p = 0; p < 2; p++) {
                float lo, hi;
                unpack2(acc[i][p], lo, hi);
                const int n = n0 + nb2 + (p << 1);
                g_txtT[n * K_TOK + m]       = lo + __ldg(&b1[n]);
                g_txtT[(n + 1) * K_TOK + m] = hi + __ldg(&b1[n + 1]);
            }
        }
    }
}

// ============ fused relu-dot with h-split ============
// part[hs][n][k] = sum_{h in split hs} relu(img[n,h]+txtT[h,k]) * W2[h]
// grid 256 = 64 n-blocks x 4 h-splits. Block: 32n x 128k x 128h.
// 128 threads, 8n x 4k per thread. h chunks of 32, double-buffered.
__global__ __launch_bounds__(128) void fused_kernel(
    const float* __restrict__ W2, float* __restrict__ part)
{
    __shared__ __align__(16) float t_s [2][32][128];  // [buf][h][k] 32 KB
    __shared__ __align__(16) u64   a2_s[2][32][32];   // [buf][h][n] (a,a) 16 KB
    __shared__ u64 w2p[128];                          // (w,w) for this h-split

    const int t  = threadIdx.x;
    const int kg = t & 31;          // 32 k-groups of 4
    const int ng = t >> 5;          // 4 n-groups of 8 (constant per warp -> broadcast)
    const int b  = blockIdx.x;
    const int nb = b & 63;
    const int hs = b >> 6;
    const int hb0 = hs * 128;
    const int nrow0 = nb * 32;

    { const float w = W2[hb0 + t]; w2p[t] = pack2(w, w); }

    // loaders
    const int tn  = t >> 3;         // 0..15 (a rows tn and tn+16)
    const int th4 = t & 7;          // a float4 along h

    float4 pt[8], pa0, pa1;

    // prefetch chunk 0
    {
        const int hbase = hb0;
        #pragma unroll
        for (int i = 0; i < 8; i++) {
            const int fid = i * 128 + t;
            pt[i] = *(const float4*)&g_txtT[(hbase + (fid >> 5)) * K_TOK + ((fid & 31) << 2)];
        }
        pa0 = *(const float4*)&g_img[(nrow0 + tn)      * H_DIM + hbase + (th4 << 2)];
        pa1 = *(const float4*)&g_img[(nrow0 + tn + 16) * H_DIM + hbase + (th4 << 2)];
    }
    // store chunk 0
    {
        #pragma unroll
        for (int i = 0; i < 8; i++) {
            const int fid = i * 128 + t;
            *(float4*)&t_s[0][fid >> 5][(fid & 31) << 2] = pt[i];
        }
        a2_s[0][(th4 << 2) + 0][tn] = pack2(pa0.x, pa0.x);
        a2_s[0][(th4 << 2) + 1][tn] = pack2(pa0.y, pa0.y);
        a2_s[0][(th4 << 2) + 2][tn] = pack2(pa0.z, pa0.z);
        a2_s[0][(th4 << 2) + 3][tn] = pack2(pa0.w, pa0.w);
        a2_s[0][(th4 << 2) + 0][tn + 16] = pack2(pa1.x, pa1.x);
        a2_s[0][(th4 << 2) + 1][tn + 16] = pack2(pa1.y, pa1.y);
        a2_s[0][(th4 << 2) + 2][tn + 16] = pack2(pa1.z, pa1.z);
        a2_s[0][(th4 << 2) + 3][tn + 16] = pack2(pa1.w, pa1.w);
    }
    __syncthreads();

    u64 acc[8][2];
    #pragma unroll
    for (int i = 0; i < 8; i++) { acc[i][0] = 0ull; acc[i][1] = 0ull; }

    for (int c = 0; c < 4; c++) {
        const int buf = c & 1;

        if (c + 1 < 4) {   // prefetch next chunk
            const int hbase = hb0 + (c + 1) * 32;
            #pragma unroll
            for (int i = 0; i < 8; i++) {
                const int fid = i * 128 + t;
                pt[i] = *(const float4*)&g_txtT[(hbase + (fid >> 5)) * K_TOK + ((fid & 31) << 2)];
            }
            pa0 = *(const float4*)&g_img[(nrow0 + tn)      * H_DIM + hbase + (th4 << 2)];
            pa1 = *(const float4*)&g_img[(nrow0 + tn + 16) * H_DIM + hbase + (th4 << 2)];
        }

        #pragma unroll 8
        for (int h = 0; h < 32; h++) {
            const u64 ww = w2p[c * 32 + h];
            const u64* ap = &a2_s[buf][h][ng << 3];
            const ulonglong2 qa0 = *(const ulonglong2*)(ap + 0);
            const ulonglong2 qa1 = *(const ulonglong2*)(ap + 2);
            const ulonglong2 qa2 = *(const ulonglong2*)(ap + 4);
            const ulonglong2 qa3 = *(const ulonglong2*)(ap + 6);
            const ulonglong2 tq  = *(const ulonglong2*)&t_s[buf][h][kg << 2];
            const u64 av[8] = {qa0.x, qa0.y, qa1.x, qa1.y, qa2.x, qa2.y, qa3.x, qa3.y};
            #pragma unroll
            for (int i = 0; i < 8; i++) {
                fma2(acc[i][0], relu2(add2(av[i], tq.x)), ww);
                fma2(acc[i][1], relu2(add2(av[i], tq.y)), ww);
            }
        }

        if (c + 1 < 4) {
            const int nbuf = buf ^ 1;
            #pragma unroll
            for (int i = 0; i < 8; i++) {
                const int fid = i * 128 + t;
                *(float4*)&t_s[nbuf][fid >> 5][(fid & 31) << 2] = pt[i];
            }
            a2_s[nbuf][(th4 << 2) + 0][tn] = pack2(pa0.x, pa0.x);
            a2_s[nbuf][(th4 << 2) + 1][tn] = pack2(pa0.y, pa0.y);
            a2_s[nbuf][(th4 << 2) + 2][tn] = pack2(pa0.z, pa0.z);
            a2_s[nbuf][(th4 << 2) + 3][tn] = pack2(pa0.w, pa0.w);
            a2_s[nbuf][(th4 << 2) + 0][tn + 16] = pack2(pa1.x, pa1.x);
            a2_s[nbuf][(th4 << 2) + 1][tn + 16] = pack2(pa1.y, pa1.y);
            a2_s[nbuf][(th4 << 2) + 2][tn + 16] = pack2(pa1.z, pa1.z);
            a2_s[nbuf][(th4 << 2) + 3][tn + 16] = pack2(pa1.w, pa1.w);
        }
        __syncthreads();
    }

    // write partials: thread covers 8 n rows x 4 k
    float* p = part + hs * (N_TOK * K_TOK);
    #pragma unroll
    for (int i = 0; i < 8; i++) {
        const int n = nrow0 + (ng << 3) + i;
        float4 v;
        unpack2(acc[i][0], v.x, v.y);
        unpack2(acc[i][1], v.z, v.w);
        *(float4*)&p[n * K_TOK + (kg << 2)] = v;
    }
}

// ============ combine: out = sum of 4 partials + b2 ============
__global__ __launch_bounds__(128) void combine_kernel(
    const float* __restrict__ b2, float* __restrict__ out)
{
    const int idx = (blockIdx.x * 128 + threadIdx.x) * 4;
    const float4 p0 = *(const float4*)&g_part[idx];
    const float4 p1 = *(const float4*)&g_part[N_TOK * K_TOK + idx];
    const float4 p2 = *(const float4*)&g_part[2 * N_TOK * K_TOK + idx];
    const float4 p3 = *(const float4*)&g_part[3 * N_TOK * K_TOK + idx];
    const float bb = b2[0];
    float4 v;
    v.x = p0.x + p1.x + p2.x + p3.x + bb;
    v.y = p0.y + p1.y + p2.y + p3.y + bb;
    v.z = p0.z + p1.z + p2.z + p3.z + bb;
    v.w = p0.w + p1.w + p2.w + p3.w + bb;
    *(float4*)&out[idx] = v;
}

extern "C" void kernel_launch(void* const* d_in, const int* in_sizes, int n_in,
                              void* d_out, int out_size) {
    const float* img = (const float*)d_in[0];   // (2048, 768)
    const float* txt = (const float*)d_in[1];   // (128, 768)
    const float* W1  = (const float*)d_in[2];   // (1536, 512)
    const float* b1  = (const float*)d_in[3];   // (512,)
    const float* W2  = (const float*)d_in[4];   // (512, 1)
    const float* b2  = (const float*)d_in[5];   // (1,)
    float* out = (float*)d_out;                 // (2048, 128)

    float* part;
    cudaGetSymbolAddress((void**)&part, g_part);

    proj_kernel<<<272, 128>>>(img, txt, W1, b1);
    fused_kernel<<<256, 128>>>(W2, part);
    combine_kernel<<<(N_TOK * K_TOK) / (128 * 4), 128>>>(b2, out);
}